// round 1
// baseline (speedup 1.0000x reference)
#include <cuda_runtime.h>
#include <math.h>
#include <float.h>

// Problem constants
#define BATCH 2
#define SEQ   2048
#define DM    1024        // model dim
#define NH    16
#define HD    64
#define FFD   4096
#define NTOK  (BATCH*SEQ) // 4096 rows

// ---------------- scratch (device globals; no allocation allowed) ----------------
__device__ float g_ln [NTOK * DM];          // 16 MB (reused for ln1 and ln2)
__device__ float g_qkv[NTOK * 3 * DM];      // 48 MB
__device__ float g_att[NTOK * DM];          // 16 MB
__device__ float g_x1 [NTOK * DM];          // 16 MB
__device__ float g_ff [NTOK * FFD];         // 64 MB

// ---------------- LayerNorm: one block per row, 256 threads -----------------
__global__ void ln_kernel(const float* __restrict__ x,
                          const float* __restrict__ g,
                          const float* __restrict__ b,
                          float* __restrict__ out)
{
    int row = blockIdx.x;
    const float* xr = x + (size_t)row * DM;
    float* orow     = out + (size_t)row * DM;
    int t = threadIdx.x;

    float v[4];
    float s = 0.f, sq = 0.f;
#pragma unroll
    for (int i = 0; i < 4; i++) {
        v[i] = xr[t + i * 256];
        s  += v[i];
        sq += v[i] * v[i];
    }
#pragma unroll
    for (int o = 16; o > 0; o >>= 1) {
        s  += __shfl_xor_sync(0xffffffffu, s,  o);
        sq += __shfl_xor_sync(0xffffffffu, sq, o);
    }
    __shared__ float rs[8], rq[8];
    int w = t >> 5, l = t & 31;
    if (l == 0) { rs[w] = s; rq[w] = sq; }
    __syncthreads();
    s = 0.f; sq = 0.f;
#pragma unroll
    for (int i = 0; i < 8; i++) { s += rs[i]; sq += rq[i]; }

    float mean = s * (1.f / DM);
    float var  = sq * (1.f / DM) - mean * mean;
    float rstd = rsqrtf(var + 1e-5f);
#pragma unroll
    for (int i = 0; i < 4; i++) {
        int idx = t + i * 256;
        orow[idx] = (v[i] - mean) * rstd * g[idx] + b[idx];
    }
}

// ---------------- SGEMM: C[M,N] = A[M,K] @ W[N,K]^T (+ epilogue) -------------
// ep: 0 = +bias; 1 = +bias then exact GELU; 2 = +bias + residual R
#define BM 128
#define BN 128
#define BK 16

__global__ __launch_bounds__(256)
void gemm_kernel(const float* __restrict__ A, const float* __restrict__ W,
                 const float* __restrict__ bias, const float* __restrict__ R,
                 float* __restrict__ C, int M, int N, int K, int ep)
{
    __shared__ __align__(16) float As[BK][BM];
    __shared__ __align__(16) float Ws[BK][BN];

    int tid = threadIdx.x;
    int tx = tid & 15, ty = tid >> 4;
    int m0 = blockIdx.y * BM, n0 = blockIdx.x * BN;

    int lr = tid >> 2;            // 0..63
    int lc = (tid & 3) << 2;      // 0,4,8,12

    const float* Aptr  = A + (size_t)(m0 + lr) * K + lc;
    const float* Aptr2 = Aptr + (size_t)64 * K;
    const float* Wptr  = W + (size_t)(n0 + lr) * K + lc;
    const float* Wptr2 = Wptr + (size_t)64 * K;

    float acc[8][8];
#pragma unroll
    for (int i = 0; i < 8; i++)
#pragma unroll
        for (int j = 0; j < 8; j++) acc[i][j] = 0.f;

    for (int k0 = 0; k0 < K; k0 += BK) {
        float4 a0 = *(const float4*)(Aptr  + k0);
        float4 a1 = *(const float4*)(Aptr2 + k0);
        float4 b0 = *(const float4*)(Wptr  + k0);
        float4 b1 = *(const float4*)(Wptr2 + k0);
        __syncthreads();  // previous compute done before overwrite
        As[lc + 0][lr] = a0.x; As[lc + 1][lr] = a0.y;
        As[lc + 2][lr] = a0.z; As[lc + 3][lr] = a0.w;
        As[lc + 0][lr + 64] = a1.x; As[lc + 1][lr + 64] = a1.y;
        As[lc + 2][lr + 64] = a1.z; As[lc + 3][lr + 64] = a1.w;
        Ws[lc + 0][lr] = b0.x; Ws[lc + 1][lr] = b0.y;
        Ws[lc + 2][lr] = b0.z; Ws[lc + 3][lr] = b0.w;
        Ws[lc + 0][lr + 64] = b1.x; Ws[lc + 1][lr + 64] = b1.y;
        Ws[lc + 2][lr + 64] = b1.z; Ws[lc + 3][lr + 64] = b1.w;
        __syncthreads();

#pragma unroll
        for (int k = 0; k < BK; k++) {
            float4 ra0 = *(const float4*)&As[k][ty * 8];
            float4 ra1 = *(const float4*)&As[k][ty * 8 + 4];
            float4 rb0 = *(const float4*)&Ws[k][tx * 8];
            float4 rb1 = *(const float4*)&Ws[k][tx * 8 + 4];
            float ra[8] = {ra0.x, ra0.y, ra0.z, ra0.w, ra1.x, ra1.y, ra1.z, ra1.w};
            float rb[8] = {rb0.x, rb0.y, rb0.z, rb0.w, rb1.x, rb1.y, rb1.z, rb1.w};
#pragma unroll
            for (int i = 0; i < 8; i++)
#pragma unroll
                for (int j = 0; j < 8; j++)
                    acc[i][j] = fmaf(ra[i], rb[j], acc[i][j]);
        }
    }

    int crow = m0 + ty * 8, ccol = n0 + tx * 8;
#pragma unroll
    for (int i = 0; i < 8; i++) {
        float* cp = C + (size_t)(crow + i) * N + ccol;
        const float* rp = (ep == 2) ? (R + (size_t)(crow + i) * N + ccol) : nullptr;
#pragma unroll
        for (int j = 0; j < 8; j++) {
            float v = acc[i][j] + bias[ccol + j];
            if (ep == 1)      v = 0.5f * v * (1.f + erff(v * 0.70710678118654752f));
            else if (ep == 2) v += rp[j];
            cp[j] = v;
        }
    }
}

// ---------------- Fused flash attention (fp32, online softmax) ---------------
// qkv layout per row (3*DM): [s*DM + h*HD + d], s in {q,k,v}
// Block: 128 threads = 16(ty) x 8(tx); QT=64 query rows, KT=32 key rows/tile.
#define QT 64
#define KT 32

__global__ __launch_bounds__(128)
void attn_kernel(const float* __restrict__ qkv, float* __restrict__ out)
{
    __shared__ __align__(16) float Qs[QT][68];
    __shared__ __align__(16) float Ks[KT][68];
    __shared__ __align__(16) float Vs[KT][68];
    __shared__ __align__(16) float Ps[QT][36];

    int bh = blockIdx.y;
    int b = bh >> 4, h = bh & 15;
    int q0 = blockIdx.x * QT;
    const float* base = qkv + (size_t)b * SEQ * (3 * DM) + h * HD;

    int tid = threadIdx.x;
    int tx = tid & 7, ty = tid >> 3;   // ty 0..15, tx 0..7
    int r0 = ty * 4;                   // 4 query rows
    int c0 = tx * 4;                   // 4 score cols
    int d0 = tx * 8;                   // 8 output dims

    // load Q tile (64 x 64)
    for (int p = tid; p < QT * 16; p += 128) {
        int r = p >> 4, c = (p & 15) << 2;
        *(float4*)&Qs[r][c] = *(const float4*)(base + (size_t)(q0 + r) * (3 * DM) + c);
    }

    float m[4], lsum[4], o[4][8];
#pragma unroll
    for (int i = 0; i < 4; i++) {
        m[i] = -FLT_MAX; lsum[i] = 0.f;
#pragma unroll
        for (int j = 0; j < 8; j++) o[i][j] = 0.f;
    }

    const float scale = 0.125f; // HD^-0.5

    for (int k0 = 0; k0 < SEQ; k0 += KT) {
        __syncthreads();  // prior reads of Ks/Vs (and Q load on first iter) done
        for (int p = tid; p < KT * 16; p += 128) {
            int r = p >> 4, c = (p & 15) << 2;
            const float* kp = base + (size_t)(k0 + r) * (3 * DM) + c;
            *(float4*)&Ks[r][c] = *(const float4*)(kp + DM);
            *(float4*)&Vs[r][c] = *(const float4*)(kp + 2 * DM);
        }
        __syncthreads();

        // S = Q K^T (4x4 per thread)
        float s[4][4];
#pragma unroll
        for (int i = 0; i < 4; i++)
#pragma unroll
            for (int j = 0; j < 4; j++) s[i][j] = 0.f;

#pragma unroll 4
        for (int d = 0; d < HD; d++) {
            float q[4], kk[4];
#pragma unroll
            for (int i = 0; i < 4; i++) q[i]  = Qs[r0 + i][d];
#pragma unroll
            for (int j = 0; j < 4; j++) kk[j] = Ks[c0 + j][d];
#pragma unroll
            for (int i = 0; i < 4; i++)
#pragma unroll
                for (int j = 0; j < 4; j++)
                    s[i][j] = fmaf(q[i], kk[j], s[i][j]);
        }

        // scale + row max (across the 8 tx lanes)
        float mt[4];
#pragma unroll
        for (int i = 0; i < 4; i++) {
            float mm = -FLT_MAX;
#pragma unroll
            for (int j = 0; j < 4; j++) {
                s[i][j] *= scale;
                mm = fmaxf(mm, s[i][j]);
            }
            mt[i] = mm;
        }
#pragma unroll
        for (int off = 1; off < 8; off <<= 1)
#pragma unroll
            for (int i = 0; i < 4; i++)
                mt[i] = fmaxf(mt[i], __shfl_xor_sync(0xffffffffu, mt[i], off));

        float alpha[4], rsum[4];
#pragma unroll
        for (int i = 0; i < 4; i++) {
            float mnew = fmaxf(m[i], mt[i]);
            alpha[i] = __expf(m[i] - mnew);
            m[i] = mnew;
            rsum[i] = 0.f;
#pragma unroll
            for (int j = 0; j < 4; j++) {
                float p = __expf(s[i][j] - mnew);
                Ps[r0 + i][c0 + j] = p;
                rsum[i] += p;
            }
        }
#pragma unroll
        for (int off = 1; off < 8; off <<= 1)
#pragma unroll
            for (int i = 0; i < 4; i++)
                rsum[i] += __shfl_xor_sync(0xffffffffu, rsum[i], off);
#pragma unroll
        for (int i = 0; i < 4; i++) {
            lsum[i] = lsum[i] * alpha[i] + rsum[i];
#pragma unroll
            for (int j = 0; j < 8; j++) o[i][j] *= alpha[i];
        }

        __syncthreads();  // Ps visible to all

        // O += P V
#pragma unroll 2
        for (int c = 0; c < KT; c++) {
            float p[4];
#pragma unroll
            for (int i = 0; i < 4; i++) p[i] = Ps[r0 + i][c];
            float4 v0 = *(const float4*)&Vs[c][d0];
            float4 v1 = *(const float4*)&Vs[c][d0 + 4];
#pragma unroll
            for (int i = 0; i < 4; i++) {
                o[i][0] = fmaf(p[i], v0.x, o[i][0]);
                o[i][1] = fmaf(p[i], v0.y, o[i][1]);
                o[i][2] = fmaf(p[i], v0.z, o[i][2]);
                o[i][3] = fmaf(p[i], v0.w, o[i][3]);
                o[i][4] = fmaf(p[i], v1.x, o[i][4]);
                o[i][5] = fmaf(p[i], v1.y, o[i][5]);
                o[i][6] = fmaf(p[i], v1.z, o[i][6]);
                o[i][7] = fmaf(p[i], v1.w, o[i][7]);
            }
        }
    }

    // finalize + write [B,N,D] with d = h*HD + d0 + j
#pragma unroll
    for (int i = 0; i < 4; i++) {
        float inv = 1.f / lsum[i];
        float4 w0, w1;
        w0.x = o[i][0] * inv; w0.y = o[i][1] * inv; w0.z = o[i][2] * inv; w0.w = o[i][3] * inv;
        w1.x = o[i][4] * inv; w1.y = o[i][5] * inv; w1.z = o[i][6] * inv; w1.w = o[i][7] * inv;
        float* op = out + (size_t)(b * SEQ + q0 + r0 + i) * DM + h * HD + d0;
        *(float4*)op       = w0;
        *(float4*)(op + 4) = w1;
    }
}

// --------------------------------- launch -----------------------------------
extern "C" void kernel_launch(void* const* d_in, const int* in_sizes, int n_in,
                              void* d_out, int out_size)
{
    const float* x      = (const float*)d_in[0];
    const float* ln1_g  = (const float*)d_in[1];
    const float* ln1_b  = (const float*)d_in[2];
    const float* w_qkv  = (const float*)d_in[3];
    const float* b_qkv  = (const float*)d_in[4];
    const float* w_proj = (const float*)d_in[5];
    const float* b_proj = (const float*)d_in[6];
    const float* ln2_g  = (const float*)d_in[7];
    const float* ln2_b  = (const float*)d_in[8];
    const float* w_fc1  = (const float*)d_in[9];
    const float* b_fc1  = (const float*)d_in[10];
    const float* w_fc2  = (const float*)d_in[11];
    const float* b_fc2  = (const float*)d_in[12];
    float* outp = (float*)d_out;

    float *ln, *qkv, *att, *x1, *ff;
    cudaGetSymbolAddress((void**)&ln,  g_ln);
    cudaGetSymbolAddress((void**)&qkv, g_qkv);
    cudaGetSymbolAddress((void**)&att, g_att);
    cudaGetSymbolAddress((void**)&x1,  g_x1);
    cudaGetSymbolAddress((void**)&ff,  g_ff);

    // 1) ln1
    ln_kernel<<<NTOK, 256>>>(x, ln1_g, ln1_b, ln);
    // 2) qkv = ln @ w_qkv^T + b_qkv            [4096 x 3072]
    gemm_kernel<<<dim3(3 * DM / BN, NTOK / BM), 256>>>(ln, w_qkv, b_qkv, nullptr, qkv,
                                                       NTOK, 3 * DM, DM, 0);
    // 3) attention                              [4096 x 1024]
    attn_kernel<<<dim3(SEQ / QT, BATCH * NH), 128>>>(qkv, att);
    // 4) x1 = att @ w_proj^T + b_proj + x
    gemm_kernel<<<dim3(DM / BN, NTOK / BM), 256>>>(att, w_proj, b_proj, x, x1,
                                                   NTOK, DM, DM, 2);
    // 5) ln2
    ln_kernel<<<NTOK, 256>>>(x1, ln2_g, ln2_b, ln);
    // 6) ff = gelu(ln @ w_fc1^T + b_fc1)        [4096 x 4096]
    gemm_kernel<<<dim3(FFD / BN, NTOK / BM), 256>>>(ln, w_fc1, b_fc1, nullptr, ff,
                                                    NTOK, FFD, DM, 1);
    // 7) out = ff @ w_fc2^T + b_fc2 + x1
    gemm_kernel<<<dim3(DM / BN, NTOK / BM), 256>>>(ff, w_fc2, b_fc2, x1, outp,
                                                   NTOK, DM, FFD, 2);
}

// round 2
// speedup vs baseline: 1.5604x; 1.5604x over previous
#include <cuda_runtime.h>
#include <math.h>
#include <float.h>
#include <stdint.h>

// Problem constants
#define BATCH 2
#define SEQ   2048
#define DM    1024
#define NH    16
#define HD    64
#define FFD   4096
#define NTOK  (BATCH*SEQ)

// ---------------- scratch (device globals) ----------------
__device__ float g_ln [NTOK * DM];
__device__ float g_qkv[NTOK * 3 * DM];
__device__ float g_att[NTOK * DM];
__device__ float g_x1 [NTOK * DM];
__device__ float g_ff [NTOK * FFD];

// ---------------- LayerNorm ----------------
__global__ void ln_kernel(const float* __restrict__ x,
                          const float* __restrict__ g,
                          const float* __restrict__ b,
                          float* __restrict__ out)
{
    int row = blockIdx.x;
    const float* xr = x + (size_t)row * DM;
    float* orow     = out + (size_t)row * DM;
    int t = threadIdx.x;

    float v[4];
    float s = 0.f, sq = 0.f;
#pragma unroll
    for (int i = 0; i < 4; i++) {
        v[i] = xr[t + i * 256];
        s  += v[i];
        sq += v[i] * v[i];
    }
#pragma unroll
    for (int o = 16; o > 0; o >>= 1) {
        s  += __shfl_xor_sync(0xffffffffu, s,  o);
        sq += __shfl_xor_sync(0xffffffffu, sq, o);
    }
    __shared__ float rs[8], rq[8];
    int w = t >> 5, l = t & 31;
    if (l == 0) { rs[w] = s; rq[w] = sq; }
    __syncthreads();
    s = 0.f; sq = 0.f;
#pragma unroll
    for (int i = 0; i < 8; i++) { s += rs[i]; sq += rq[i]; }

    float mean = s * (1.f / DM);
    float var  = sq * (1.f / DM) - mean * mean;
    float rstd = rsqrtf(var + 1e-5f);
#pragma unroll
    for (int i = 0; i < 4; i++) {
        int idx = t + i * 256;
        orow[idx] = (v[i] - mean) * rstd * g[idx] + b[idx];
    }
}

// ---------------- TF32 tensor-core GEMM ----------------
// C[M,N] = A[M,K] @ W[N,K]^T (+ epilogue). ep: 0=+bias; 1=+bias,GELU; 2=+bias+R
#define BM 128
#define BN 128
#define BK 16
#define SST 20   // BK + 4 pad: (20*r+q) mod 32 all-distinct -> conflict-free LDS

__device__ __forceinline__ uint32_t f2tf(float f) {
    uint32_t r; asm("cvt.rna.tf32.f32 %0, %1;\n" : "=r"(r) : "f"(f)); return r;
}

#define CPA16(dst, src) do { \
    uint32_t _d = (uint32_t)__cvta_generic_to_shared(dst); \
    asm volatile("cp.async.cg.shared.global [%0], [%1], 16;\n" :: "r"(_d), "l"(src)); \
} while (0)

__global__ __launch_bounds__(256)
void gemm_tf32(const float* __restrict__ A, const float* __restrict__ W,
               const float* __restrict__ bias, const float* __restrict__ R,
               float* __restrict__ C, int M, int N, int K, int ep)
{
    __shared__ __align__(16) float As[2][BM][SST];
    __shared__ __align__(16) float Ws[2][BN][SST];

    int tid  = threadIdx.x;
    int lane = tid & 31, warp = tid >> 5;
    int wm = warp >> 2, wn = warp & 3;         // warp grid 2(m) x 4(n)
    int r  = lane >> 2, q = lane & 3;          // groupID / threadID-in-group
    int m0 = blockIdx.y * BM, n0 = blockIdx.x * BN;

    // copy indexing: 512 16B-chunks per matrix per stage; 2 per thread
    int c0r = (tid * 2) >> 2;                  // chunk row for pair start
    int c0s = ((tid * 2) & 3) * 4;             // float offset within row (0,4,8,12)
    // thread copies chunks 2*tid and 2*tid+1 (same row, adjacent segs)

    float acc[4][4][4];
#pragma unroll
    for (int i = 0; i < 4; i++)
#pragma unroll
        for (int j = 0; j < 4; j++)
#pragma unroll
            for (int c = 0; c < 4; c++) acc[i][j][c] = 0.f;

    const int T = K / BK;

    // prologue: stage 0
    {
        const float* srcA = A + (size_t)(m0 + c0r) * K + c0s;
        const float* srcW = W + (size_t)(n0 + c0r) * K + c0s;
        CPA16(&As[0][c0r][c0s],     srcA);
        CPA16(&As[0][c0r][c0s + 4], srcA + 4);
        CPA16(&Ws[0][c0r][c0s],     srcW);
        CPA16(&Ws[0][c0r][c0s + 4], srcW + 4);
        asm volatile("cp.async.commit_group;\n");
    }

    for (int kt = 0; kt < T; kt++) {
        asm volatile("cp.async.wait_group 0;\n");
        __syncthreads();

        if (kt + 1 < T) {
            int nb = (kt + 1) & 1;
            int k0 = (kt + 1) * BK;
            const float* srcA = A + (size_t)(m0 + c0r) * K + k0 + c0s;
            const float* srcW = W + (size_t)(n0 + c0r) * K + k0 + c0s;
            CPA16(&As[nb][c0r][c0s],     srcA);
            CPA16(&As[nb][c0r][c0s + 4], srcA + 4);
            CPA16(&Ws[nb][c0r][c0s],     srcW);
            CPA16(&Ws[nb][c0r][c0s + 4], srcW + 4);
            asm volatile("cp.async.commit_group;\n");
        }

        int b = kt & 1;
#pragma unroll
        for (int s = 0; s < 2; s++) {
            int k = s * 8;
            uint32_t af[4][4], bf[4][2];
#pragma unroll
            for (int i = 0; i < 4; i++) {
                int mr = wm * 64 + i * 16 + r;
                af[i][0] = f2tf(As[b][mr    ][k + q]);
                af[i][1] = f2tf(As[b][mr + 8][k + q]);
                af[i][2] = f2tf(As[b][mr    ][k + q + 4]);
                af[i][3] = f2tf(As[b][mr + 8][k + q + 4]);
            }
#pragma unroll
            for (int j = 0; j < 4; j++) {
                int nr = wn * 32 + j * 8 + r;
                bf[j][0] = f2tf(Ws[b][nr][k + q]);
                bf[j][1] = f2tf(Ws[b][nr][k + q + 4]);
            }
#pragma unroll
            for (int i = 0; i < 4; i++)
#pragma unroll
                for (int j = 0; j < 4; j++)
                    asm volatile(
                        "mma.sync.aligned.m16n8k8.row.col.f32.tf32.tf32.f32 "
                        "{%0,%1,%2,%3}, {%4,%5,%6,%7}, {%8,%9}, {%0,%1,%2,%3};\n"
                        : "+f"(acc[i][j][0]), "+f"(acc[i][j][1]),
                          "+f"(acc[i][j][2]), "+f"(acc[i][j][3])
                        : "r"(af[i][0]), "r"(af[i][1]), "r"(af[i][2]), "r"(af[i][3]),
                          "r"(bf[j][0]), "r"(bf[j][1]));
        }
        __syncthreads();
    }

    // epilogue: c0,c1 at (row, col..col+1); c2,c3 at (row+8, ...)
    int row0 = m0 + wm * 64 + r;
    int col0 = n0 + wn * 32 + 2 * q;
#pragma unroll
    for (int i = 0; i < 4; i++) {
#pragma unroll
        for (int j = 0; j < 4; j++) {
            int cc = col0 + j * 8;
            float bx = bias[cc], by = bias[cc + 1];
#pragma unroll
            for (int h = 0; h < 2; h++) {
                int rr = row0 + i * 16 + h * 8;
                float vx = acc[i][j][2 * h]     + bx;
                float vy = acc[i][j][2 * h + 1] + by;
                if (ep == 1) {
                    vx = 0.5f * vx * (1.f + erff(vx * 0.70710678118654752f));
                    vy = 0.5f * vy * (1.f + erff(vy * 0.70710678118654752f));
                } else if (ep == 2) {
                    const float* rp = R + (size_t)rr * N + cc;
                    vx += rp[0]; vy += rp[1];
                }
                float2 o2; o2.x = vx; o2.y = vy;
                *(float2*)(C + (size_t)rr * N + cc) = o2;
            }
        }
    }
}

// ---------------- Fused flash attention (fp32) ----------------
#define QT 64
#define KT 32

__global__ __launch_bounds__(128)
void attn_kernel(const float* __restrict__ qkv, float* __restrict__ out)
{
    __shared__ __align__(16) float Qs[QT][68];
    __shared__ __align__(16) float Ks[KT][68];
    __shared__ __align__(16) float Vs[KT][68];
    __shared__ __align__(16) float Ps[QT][36];

    int bh = blockIdx.y;
    int b = bh >> 4, h = bh & 15;
    int q0 = blockIdx.x * QT;
    const float* base = qkv + (size_t)b * SEQ * (3 * DM) + h * HD;

    int tid = threadIdx.x;
    int tx = tid & 7, ty = tid >> 3;
    int r0 = ty * 4;
    int c0 = tx * 4;
    int d0 = tx * 8;

    for (int p = tid; p < QT * 16; p += 128) {
        int r = p >> 4, c = (p & 15) << 2;
        *(float4*)&Qs[r][c] = *(const float4*)(base + (size_t)(q0 + r) * (3 * DM) + c);
    }

    float m[4], lsum[4], o[4][8];
#pragma unroll
    for (int i = 0; i < 4; i++) {
        m[i] = -FLT_MAX; lsum[i] = 0.f;
#pragma unroll
        for (int j = 0; j < 8; j++) o[i][j] = 0.f;
    }

    const float scale = 0.125f;

    for (int k0 = 0; k0 < SEQ; k0 += KT) {
        __syncthreads();
        for (int p = tid; p < KT * 16; p += 128) {
            int r = p >> 4, c = (p & 15) << 2;
            const float* kp = base + (size_t)(k0 + r) * (3 * DM) + c;
            *(float4*)&Ks[r][c] = *(const float4*)(kp + DM);
            *(float4*)&Vs[r][c] = *(const float4*)(kp + 2 * DM);
        }
        __syncthreads();

        float s[4][4];
#pragma unroll
        for (int i = 0; i < 4; i++)
#pragma unroll
            for (int j = 0; j < 4; j++) s[i][j] = 0.f;

#pragma unroll 4
        for (int d = 0; d < HD; d++) {
            float qv[4], kk[4];
#pragma unroll
            for (int i = 0; i < 4; i++) qv[i] = Qs[r0 + i][d];
#pragma unroll
            for (int j = 0; j < 4; j++) kk[j] = Ks[c0 + j][d];
#pragma unroll
            for (int i = 0; i < 4; i++)
#pragma unroll
                for (int j = 0; j < 4; j++)
                    s[i][j] = fmaf(qv[i], kk[j], s[i][j]);
        }

        float mt[4];
#pragma unroll
        for (int i = 0; i < 4; i++) {
            float mm = -FLT_MAX;
#pragma unroll
            for (int j = 0; j < 4; j++) {
                s[i][j] *= scale;
                mm = fmaxf(mm, s[i][j]);
            }
            mt[i] = mm;
        }
#pragma unroll
        for (int off = 1; off < 8; off <<= 1)
#pragma unroll
            for (int i = 0; i < 4; i++)
                mt[i] = fmaxf(mt[i], __shfl_xor_sync(0xffffffffu, mt[i], off));

        float alpha[4], rsum[4];
#pragma unroll
        for (int i = 0; i < 4; i++) {
            float mnew = fmaxf(m[i], mt[i]);
            alpha[i] = __expf(m[i] - mnew);
            m[i] = mnew;
            rsum[i] = 0.f;
#pragma unroll
            for (int j = 0; j < 4; j++) {
                float p = __expf(s[i][j] - mnew);
                Ps[r0 + i][c0 + j] = p;
                rsum[i] += p;
            }
        }
#pragma unroll
        for (int off = 1; off < 8; off <<= 1)
#pragma unroll
            for (int i = 0; i < 4; i++)
                rsum[i] += __shfl_xor_sync(0xffffffffu, rsum[i], off);
#pragma unroll
        for (int i = 0; i < 4; i++) {
            lsum[i] = lsum[i] * alpha[i] + rsum[i];
#pragma unroll
            for (int j = 0; j < 8; j++) o[i][j] *= alpha[i];
        }

        __syncthreads();

#pragma unroll 2
        for (int c = 0; c < KT; c++) {
            float p[4];
#pragma unroll
            for (int i = 0; i < 4; i++) p[i] = Ps[r0 + i][c];
            float4 v0 = *(const float4*)&Vs[c][d0];
            float4 v1 = *(const float4*)&Vs[c][d0 + 4];
#pragma unroll
            for (int i = 0; i < 4; i++) {
                o[i][0] = fmaf(p[i], v0.x, o[i][0]);
                o[i][1] = fmaf(p[i], v0.y, o[i][1]);
                o[i][2] = fmaf(p[i], v0.z, o[i][2]);
                o[i][3] = fmaf(p[i], v0.w, o[i][3]);
                o[i][4] = fmaf(p[i], v1.x, o[i][4]);
                o[i][5] = fmaf(p[i], v1.y, o[i][5]);
                o[i][6] = fmaf(p[i], v1.z, o[i][6]);
                o[i][7] = fmaf(p[i], v1.w, o[i][7]);
            }
        }
    }

#pragma unroll
    for (int i = 0; i < 4; i++) {
        float inv = 1.f / lsum[i];
        float4 w0, w1;
        w0.x = o[i][0] * inv; w0.y = o[i][1] * inv; w0.z = o[i][2] * inv; w0.w = o[i][3] * inv;
        w1.x = o[i][4] * inv; w1.y = o[i][5] * inv; w1.z = o[i][6] * inv; w1.w = o[i][7] * inv;
        float* op = out + (size_t)(b * SEQ + q0 + r0 + i) * DM + h * HD + d0;
        *(float4*)op       = w0;
        *(float4*)(op + 4) = w1;
    }
}

// --------------------------------- launch -----------------------------------
extern "C" void kernel_launch(void* const* d_in, const int* in_sizes, int n_in,
                              void* d_out, int out_size)
{
    const float* x      = (const float*)d_in[0];
    const float* ln1_g  = (const float*)d_in[1];
    const float* ln1_b  = (const float*)d_in[2];
    const float* w_qkv  = (const float*)d_in[3];
    const float* b_qkv  = (const float*)d_in[4];
    const float* w_proj = (const float*)d_in[5];
    const float* b_proj = (const float*)d_in[6];
    const float* ln2_g  = (const float*)d_in[7];
    const float* ln2_b  = (const float*)d_in[8];
    const float* w_fc1  = (const float*)d_in[9];
    const float* b_fc1  = (const float*)d_in[10];
    const float* w_fc2  = (const float*)d_in[11];
    const float* b_fc2  = (const float*)d_in[12];
    float* outp = (float*)d_out;

    float *ln, *qkv, *att, *x1, *ff;
    cudaGetSymbolAddress((void**)&ln,  g_ln);
    cudaGetSymbolAddress((void**)&qkv, g_qkv);
    cudaGetSymbolAddress((void**)&att, g_att);
    cudaGetSymbolAddress((void**)&x1,  g_x1);
    cudaGetSymbolAddress((void**)&ff,  g_ff);

    ln_kernel<<<NTOK, 256>>>(x, ln1_g, ln1_b, ln);
    gemm_tf32<<<dim3(3 * DM / BN, NTOK / BM), 256>>>(ln, w_qkv, b_qkv, nullptr, qkv,
                                                     NTOK, 3 * DM, DM, 0);
    attn_kernel<<<dim3(SEQ / QT, BATCH * NH), 128>>>(qkv, att);
    gemm_tf32<<<dim3(DM / BN, NTOK / BM), 256>>>(att, w_proj, b_proj, x, x1,
                                                 NTOK, DM, DM, 2);
    ln_kernel<<<NTOK, 256>>>(x1, ln2_g, ln2_b, ln);
    gemm_tf32<<<dim3(FFD / BN, NTOK / BM), 256>>>(ln, w_fc1, b_fc1, nullptr, ff,
                                                  NTOK, FFD, DM, 1);
    gemm_tf32<<<dim3(DM / BN, NTOK / BM), 256>>>(ff, w_fc2, b_fc2, x1, outp,
                                                 NTOK, DM, FFD, 2);
}

// round 3
// speedup vs baseline: 2.9790x; 1.9092x over previous
#include <cuda_runtime.h>
#include <math.h>
#include <float.h>
#include <stdint.h>

// Problem constants
#define BATCH 2
#define SEQ   2048
#define DM    1024
#define NH    16
#define HD    64
#define FFD   4096
#define NTOK  (BATCH*SEQ)

// ---------------- scratch (device globals) ----------------
__device__ float g_ln [NTOK * DM];
__device__ float g_qkv[NTOK * 3 * DM];
__device__ float g_att[NTOK * DM];
__device__ float g_x1 [NTOK * DM];
__device__ float g_ff [NTOK * FFD];
// rounded weights: w_qkv(3D*D) | w_proj(D*D) | w_fc1(FF*D) | w_fc2(D*FF)
#define WQ_OFF 0
#define WP_OFF (3*DM*DM)
#define W1_OFF (WP_OFF + DM*DM)
#define W2_OFF (W1_OFF + FFD*DM)
#define W_TOT  (W2_OFF + DM*FFD)
__device__ float g_w[W_TOT];

// ---------------- helpers ----------------
__device__ __forceinline__ float rtf(float x) {           // round to tf32, as float
    uint32_t u; asm("cvt.rna.tf32.f32 %0, %1;\n" : "=r"(u) : "f"(x));
    return __uint_as_float(u);
}
__device__ __forceinline__ uint32_t fbits(float x) { return __float_as_uint(x); }

__device__ __forceinline__ void mma_tf32(float* c, uint32_t a0, uint32_t a1,
                                         uint32_t a2, uint32_t a3,
                                         uint32_t b0, uint32_t b1) {
    asm volatile(
        "mma.sync.aligned.m16n8k8.row.col.f32.tf32.tf32.f32 "
        "{%0,%1,%2,%3}, {%4,%5,%6,%7}, {%8,%9}, {%0,%1,%2,%3};\n"
        : "+f"(c[0]), "+f"(c[1]), "+f"(c[2]), "+f"(c[3])
        : "r"(a0), "r"(a1), "r"(a2), "r"(a3), "r"(b0), "r"(b1));
}

// exp via exp2 poly on FMA pipe (no MUFU). Valid for x <= 0. ~1e-7 rel.
__device__ __forceinline__ float fast_exp(float x) {
    float t = x * 1.4426950408889634f;
    t = fmaxf(t, -120.f);
    float fn = t + 12582912.f;                  // round-to-nearest-int magic
    int   n  = __float_as_int(fn) - 0x4B400000;
    float f  = t - (fn - 12582912.f);           // f in [-0.5, 0.5]
    float p  = 1.535336188319500e-4f;
    p = fmaf(p, f, 1.339887440266574e-3f);
    p = fmaf(p, f, 9.618437357674640e-3f);
    p = fmaf(p, f, 5.550332471162809e-2f);
    p = fmaf(p, f, 2.402264791363012e-1f);
    p = fmaf(p, f, 6.931472028550421e-1f);
    p = fmaf(p, f, 1.0f);
    return p * __int_as_float((n + 127) << 23);
}

// ---------------- tf32 pre-rounding (weights) ----------------
__global__ void round4_kernel(const float* __restrict__ in, float* __restrict__ out, int n4)
{
    int i = blockIdx.x * blockDim.x + threadIdx.x;
    if (i < n4) {
        float4 v = ((const float4*)in)[i];
        v.x = rtf(v.x); v.y = rtf(v.y); v.z = rtf(v.z); v.w = rtf(v.w);
        ((float4*)out)[i] = v;
    }
}

// ---------------- LayerNorm (outputs tf32-rounded) ----------------
__global__ void ln_kernel(const float* __restrict__ x,
                          const float* __restrict__ g,
                          const float* __restrict__ b,
                          float* __restrict__ out)
{
    int row = blockIdx.x;
    const float* xr = x + (size_t)row * DM;
    float* orow     = out + (size_t)row * DM;
    int t = threadIdx.x;

    float v[4];
    float s = 0.f, sq = 0.f;
#pragma unroll
    for (int i = 0; i < 4; i++) {
        v[i] = xr[t + i * 256];
        s  += v[i];
        sq += v[i] * v[i];
    }
#pragma unroll
    for (int o = 16; o > 0; o >>= 1) {
        s  += __shfl_xor_sync(0xffffffffu, s,  o);
        sq += __shfl_xor_sync(0xffffffffu, sq, o);
    }
    __shared__ float rs[8], rq[8];
    int w = t >> 5, l = t & 31;
    if (l == 0) { rs[w] = s; rq[w] = sq; }
    __syncthreads();
    s = 0.f; sq = 0.f;
#pragma unroll
    for (int i = 0; i < 8; i++) { s += rs[i]; sq += rq[i]; }

    float mean = s * (1.f / DM);
    float var  = sq * (1.f / DM) - mean * mean;
    float rstd = rsqrtf(var + 1e-5f);
#pragma unroll
    for (int i = 0; i < 4; i++) {
        int idx = t + i * 256;
        orow[idx] = rtf((v[i] - mean) * rstd * g[idx] + b[idx]);
    }
}

// ---------------- TF32 tensor-core GEMM (pre-rounded inputs) ----------------
// C[M,N] = A[M,K] @ W[N,K]^T (+ epilogue). ep: 0=+bias,round; 1=+bias,GELU,round; 2=+bias+R
#define BM 128
#define BN 128
#define BK 16
#define SST 20

#define CPA16(dst, src) do { \
    uint32_t _d = (uint32_t)__cvta_generic_to_shared(dst); \
    asm volatile("cp.async.cg.shared.global [%0], [%1], 16;\n" :: "r"(_d), "l"(src)); \
} while (0)

__global__ __launch_bounds__(256)
void gemm_tf32(const float* __restrict__ A, const float* __restrict__ W,
               const float* __restrict__ bias, const float* __restrict__ R,
               float* __restrict__ C, int M, int N, int K, int ep)
{
    __shared__ __align__(16) float As[2][BM][SST];
    __shared__ __align__(16) float Ws[2][BN][SST];

    int tid  = threadIdx.x;
    int lane = tid & 31, warp = tid >> 5;
    int wm = warp >> 2, wn = warp & 3;
    int r  = lane >> 2, q = lane & 3;
    int m0 = blockIdx.y * BM, n0 = blockIdx.x * BN;

    int c0r = (tid * 2) >> 2;
    int c0s = ((tid * 2) & 3) * 4;

    float acc[4][4][4];
#pragma unroll
    for (int i = 0; i < 4; i++)
#pragma unroll
        for (int j = 0; j < 4; j++)
#pragma unroll
            for (int c = 0; c < 4; c++) acc[i][j][c] = 0.f;

    const int T = K / BK;

    {
        const float* srcA = A + (size_t)(m0 + c0r) * K + c0s;
        const float* srcW = W + (size_t)(n0 + c0r) * K + c0s;
        CPA16(&As[0][c0r][c0s],     srcA);
        CPA16(&As[0][c0r][c0s + 4], srcA + 4);
        CPA16(&Ws[0][c0r][c0s],     srcW);
        CPA16(&Ws[0][c0r][c0s + 4], srcW + 4);
        asm volatile("cp.async.commit_group;\n");
    }

    for (int kt = 0; kt < T; kt++) {
        asm volatile("cp.async.wait_group 0;\n");
        __syncthreads();

        if (kt + 1 < T) {
            int nb = (kt + 1) & 1;
            int k0 = (kt + 1) * BK;
            const float* srcA = A + (size_t)(m0 + c0r) * K + k0 + c0s;
            const float* srcW = W + (size_t)(n0 + c0r) * K + k0 + c0s;
            CPA16(&As[nb][c0r][c0s],     srcA);
            CPA16(&As[nb][c0r][c0s + 4], srcA + 4);
            CPA16(&Ws[nb][c0r][c0s],     srcW);
            CPA16(&Ws[nb][c0r][c0s + 4], srcW + 4);
            asm volatile("cp.async.commit_group;\n");
        }

        int b = kt & 1;
#pragma unroll
        for (int s = 0; s < 2; s++) {
            int k = s * 8;
            uint32_t af[4][4], bf[4][2];
#pragma unroll
            for (int i = 0; i < 4; i++) {
                int mr = wm * 64 + i * 16 + r;
                af[i][0] = fbits(As[b][mr    ][k + q]);
                af[i][1] = fbits(As[b][mr + 8][k + q]);
                af[i][2] = fbits(As[b][mr    ][k + q + 4]);
                af[i][3] = fbits(As[b][mr + 8][k + q + 4]);
            }
#pragma unroll
            for (int j = 0; j < 4; j++) {
                int nr = wn * 32 + j * 8 + r;
                bf[j][0] = fbits(Ws[b][nr][k + q]);
                bf[j][1] = fbits(Ws[b][nr][k + q + 4]);
            }
#pragma unroll
            for (int i = 0; i < 4; i++)
#pragma unroll
                for (int j = 0; j < 4; j++)
                    mma_tf32(acc[i][j], af[i][0], af[i][1], af[i][2], af[i][3],
                             bf[j][0], bf[j][1]);
        }
        __syncthreads();
    }

    int row0 = m0 + wm * 64 + r;
    int col0 = n0 + wn * 32 + 2 * q;
#pragma unroll
    for (int i = 0; i < 4; i++) {
#pragma unroll
        for (int j = 0; j < 4; j++) {
            int cc = col0 + j * 8;
            float bx = bias[cc], by = bias[cc + 1];
#pragma unroll
            for (int h = 0; h < 2; h++) {
                int rr = row0 + i * 16 + h * 8;
                float vx = acc[i][j][2 * h]     + bx;
                float vy = acc[i][j][2 * h + 1] + by;
                if (ep == 1) {
                    vx = rtf(0.5f * vx * (1.f + erff(vx * 0.70710678118654752f)));
                    vy = rtf(0.5f * vy * (1.f + erff(vy * 0.70710678118654752f)));
                } else if (ep == 2) {
                    const float* rp = R + (size_t)rr * N + cc;
                    vx += rp[0]; vy += rp[1];
                } else {
                    vx = rtf(vx); vy = rtf(vy);
                }
                float2 o2; o2.x = vx; o2.y = vy;
                *(float2*)(C + (size_t)rr * N + cc) = o2;
            }
        }
    }
}

// ---------------- Tensor-core flash attention (TF32 mma + poly exp) ----------
// Block: 128 threads = 4 warps. QT=64 (16 rows/warp), KT=64. HD=64.
// smem: Qs,Ks,Vs,Ps each [64][68] floats (dynamic; 69632 B total).
#define ATT_SMEM (4 * 64 * 68 * 4)

__global__ __launch_bounds__(128)
void attn_tc(const float* __restrict__ qkv, float* __restrict__ out)
{
    extern __shared__ float sm[];
    float (*Qs)[68] = reinterpret_cast<float(*)[68]>(sm);
    float (*Ks)[68] = reinterpret_cast<float(*)[68]>(sm + 64 * 68);
    float (*Vs)[68] = reinterpret_cast<float(*)[68]>(sm + 2 * 64 * 68);
    float (*Ps)[68] = reinterpret_cast<float(*)[68]>(sm + 3 * 64 * 68);

    int bh = blockIdx.y;
    int b = bh >> 4, h = bh & 15;
    int q0 = blockIdx.x * 64;
    const float* base = qkv + (size_t)b * SEQ * (3 * DM) + h * HD;

    int tid = threadIdx.x;
    int lane = tid & 31, warp = tid >> 5;
    int r = lane >> 2, q = lane & 3;
    int wrow = warp * 16;

    // load Q tile (already tf32-rounded upstream)
    for (int p = tid; p < 64 * 16; p += 128) {
        int rr = p >> 4, cc = (p & 15) << 2;
        *(float4*)&Qs[rr][cc] = *(const float4*)(base + (size_t)(q0 + rr) * (3 * DM) + cc);
    }

    float oacc[8][4];
#pragma unroll
    for (int n = 0; n < 8; n++)
#pragma unroll
        for (int c = 0; c < 4; c++) oacc[n][c] = 0.f;
    float m0v = -1e30f, m1v = -1e30f, l0v = 0.f, l1v = 0.f;
    const float scale = 0.125f;

    for (int k0 = 0; k0 < SEQ; k0 += 64) {
        __syncthreads();
        for (int p = tid; p < 64 * 16; p += 128) {
            int rr = p >> 4, cc = (p & 15) << 2;
            const float* kp = base + (size_t)(k0 + rr) * (3 * DM) + cc;
            *(float4*)&Ks[rr][cc] = *(const float4*)(kp + DM);
            *(float4*)&Vs[rr][cc] = *(const float4*)(kp + 2 * DM);
        }
        __syncthreads();

        // ---- S = Q K^T ----
        float sacc[8][4];
#pragma unroll
        for (int n = 0; n < 8; n++)
#pragma unroll
            for (int c = 0; c < 4; c++) sacc[n][c] = 0.f;

#pragma unroll
        for (int kk = 0; kk < 8; kk++) {
            int k = kk * 8;
            uint32_t a0 = fbits(Qs[wrow + r    ][k + q]);
            uint32_t a1 = fbits(Qs[wrow + r + 8][k + q]);
            uint32_t a2 = fbits(Qs[wrow + r    ][k + q + 4]);
            uint32_t a3 = fbits(Qs[wrow + r + 8][k + q + 4]);
#pragma unroll
            for (int n = 0; n < 8; n++) {
                uint32_t b0 = fbits(Ks[n * 8 + r][k + q]);
                uint32_t b1 = fbits(Ks[n * 8 + r][k + q + 4]);
                mma_tf32(sacc[n], a0, a1, a2, a3, b0, b1);
            }
        }

        // ---- online softmax ----
        float vm0 = -1e30f, vm1 = -1e30f;
#pragma unroll
        for (int n = 0; n < 8; n++) {
            sacc[n][0] *= scale; sacc[n][1] *= scale;
            sacc[n][2] *= scale; sacc[n][3] *= scale;
            vm0 = fmaxf(vm0, fmaxf(sacc[n][0], sacc[n][1]));
            vm1 = fmaxf(vm1, fmaxf(sacc[n][2], sacc[n][3]));
        }
#pragma unroll
        for (int off = 1; off < 4; off <<= 1) {
            vm0 = fmaxf(vm0, __shfl_xor_sync(0xffffffffu, vm0, off));
            vm1 = fmaxf(vm1, __shfl_xor_sync(0xffffffffu, vm1, off));
        }
        float mn0 = fmaxf(m0v, vm0), mn1 = fmaxf(m1v, vm1);
        float al0 = fast_exp(m0v - mn0), al1 = fast_exp(m1v - mn1);
        m0v = mn0; m1v = mn1;

        float rs0 = 0.f, rs1 = 0.f;
#pragma unroll
        for (int n = 0; n < 8; n++) {
            float p00 = rtf(fast_exp(sacc[n][0] - mn0));
            float p01 = rtf(fast_exp(sacc[n][1] - mn0));
            float p10 = rtf(fast_exp(sacc[n][2] - mn1));
            float p11 = rtf(fast_exp(sacc[n][3] - mn1));
            rs0 += p00 + p01;
            rs1 += p10 + p11;
            float2 lo; lo.x = p00; lo.y = p01;
            float2 hi; hi.x = p10; hi.y = p11;
            *(float2*)&Ps[wrow + r    ][n * 8 + 2 * q] = lo;
            *(float2*)&Ps[wrow + r + 8][n * 8 + 2 * q] = hi;
        }
#pragma unroll
        for (int off = 1; off < 4; off <<= 1) {
            rs0 += __shfl_xor_sync(0xffffffffu, rs0, off);
            rs1 += __shfl_xor_sync(0xffffffffu, rs1, off);
        }
        l0v = l0v * al0 + rs0;
        l1v = l1v * al1 + rs1;
#pragma unroll
        for (int n = 0; n < 8; n++) {
            oacc[n][0] *= al0; oacc[n][1] *= al0;
            oacc[n][2] *= al1; oacc[n][3] *= al1;
        }
        __syncwarp();

        // ---- O += P V ----
#pragma unroll
        for (int kk = 0; kk < 8; kk++) {
            int k = kk * 8;
            uint32_t a0 = fbits(Ps[wrow + r    ][k + q]);
            uint32_t a1 = fbits(Ps[wrow + r + 8][k + q]);
            uint32_t a2 = fbits(Ps[wrow + r    ][k + q + 4]);
            uint32_t a3 = fbits(Ps[wrow + r + 8][k + q + 4]);
#pragma unroll
            for (int n = 0; n < 8; n++) {
                uint32_t b0 = fbits(Vs[k + q    ][n * 8 + r]);
                uint32_t b1 = fbits(Vs[k + q + 4][n * 8 + r]);
                mma_tf32(oacc[n], a0, a1, a2, a3, b0, b1);
            }
        }
        __syncwarp();
    }

    // ---- finalize (rounded for the proj GEMM) ----
    float inv0 = __fdividef(1.f, l0v);
    float inv1 = __fdividef(1.f, l1v);
    int row0 = b * SEQ + q0 + wrow + r;
#pragma unroll
    for (int n = 0; n < 8; n++) {
        int col = h * HD + n * 8 + 2 * q;
        float2 lo; lo.x = rtf(oacc[n][0] * inv0); lo.y = rtf(oacc[n][1] * inv0);
        float2 hi; hi.x = rtf(oacc[n][2] * inv1); hi.y = rtf(oacc[n][3] * inv1);
        *(float2*)(out + (size_t)row0 * DM + col)       = lo;
        *(float2*)(out + (size_t)(row0 + 8) * DM + col) = hi;
    }
}

// --------------------------------- launch -----------------------------------
extern "C" void kernel_launch(void* const* d_in, const int* in_sizes, int n_in,
                              void* d_out, int out_size)
{
    const float* x      = (const float*)d_in[0];
    const float* ln1_g  = (const float*)d_in[1];
    const float* ln1_b  = (const float*)d_in[2];
    const float* w_qkv  = (const float*)d_in[3];
    const float* b_qkv  = (const float*)d_in[4];
    const float* w_proj = (const float*)d_in[5];
    const float* b_proj = (const float*)d_in[6];
    const float* ln2_g  = (const float*)d_in[7];
    const float* ln2_b  = (const float*)d_in[8];
    const float* w_fc1  = (const float*)d_in[9];
    const float* b_fc1  = (const float*)d_in[10];
    const float* w_fc2  = (const float*)d_in[11];
    const float* b_fc2  = (const float*)d_in[12];
    float* outp = (float*)d_out;

    float *ln, *qkv, *att, *x1, *ff, *w;
    cudaGetSymbolAddress((void**)&ln,  g_ln);
    cudaGetSymbolAddress((void**)&qkv, g_qkv);
    cudaGetSymbolAddress((void**)&att, g_att);
    cudaGetSymbolAddress((void**)&x1,  g_x1);
    cudaGetSymbolAddress((void**)&ff,  g_ff);
    cudaGetSymbolAddress((void**)&w,   g_w);

    static bool attr_set = false;
    if (!attr_set) {
        cudaFuncSetAttribute(attn_tc, cudaFuncAttributeMaxDynamicSharedMemorySize, ATT_SMEM);
        attr_set = true;
    }

    // pre-round weights to tf32
    round4_kernel<<<(3*DM*DM/4 + 255)/256, 256>>>(w_qkv,  w + WQ_OFF, 3*DM*DM/4);
    round4_kernel<<<(DM*DM/4   + 255)/256, 256>>>(w_proj, w + WP_OFF, DM*DM/4);
    round4_kernel<<<(FFD*DM/4  + 255)/256, 256>>>(w_fc1,  w + W1_OFF, FFD*DM/4);
    round4_kernel<<<(DM*FFD/4  + 255)/256, 256>>>(w_fc2,  w + W2_OFF, DM*FFD/4);

    ln_kernel<<<NTOK, 256>>>(x, ln1_g, ln1_b, ln);
    gemm_tf32<<<dim3(3 * DM / BN, NTOK / BM), 256>>>(ln, w + WQ_OFF, b_qkv, nullptr, qkv,
                                                     NTOK, 3 * DM, DM, 0);
    attn_tc<<<dim3(SEQ / 64, BATCH * NH), 128, ATT_SMEM>>>(qkv, att);
    gemm_tf32<<<dim3(DM / BN, NTOK / BM), 256>>>(att, w + WP_OFF, b_proj, x, x1,
                                                 NTOK, DM, DM, 2);
    ln_kernel<<<NTOK, 256>>>(x1, ln2_g, ln2_b, ln);
    gemm_tf32<<<dim3(FFD / BN, NTOK / BM), 256>>>(ln, w + W1_OFF, b_fc1, nullptr, ff,
                                                  NTOK, FFD, DM, 1);
    gemm_tf32<<<dim3(DM / BN, NTOK / BM), 256>>>(ff, w + W2_OFF, b_fc2, x1, outp,
                                                 NTOK, DM, FFD, 2);
}

// round 5
// speedup vs baseline: 2.9958x; 1.0057x over previous
#include <cuda_runtime.h>
#include <math.h>
#include <float.h>
#include <stdint.h>

// Problem constants
#define BATCH 2
#define SEQ   2048
#define DM    1024
#define NH    16
#define HD    64
#define FFD   4096
#define NTOK  (BATCH*SEQ)

// ---------------- scratch (device globals) ----------------
__device__ float g_ln [NTOK * DM];
__device__ float g_qkv[NTOK * 3 * DM];
__device__ float g_att[NTOK * DM];
__device__ float g_x1 [NTOK * DM];
__device__ float g_ff [NTOK * FFD];
#define WQ_OFF 0
#define WP_OFF (3*DM*DM)
#define W1_OFF (WP_OFF + DM*DM)
#define W2_OFF (W1_OFF + FFD*DM)
#define W_TOT  (W2_OFF + DM*FFD)
__device__ float g_w[W_TOT];

// ---------------- helpers ----------------
__device__ __forceinline__ float rtf(float x) {
    uint32_t u; asm("cvt.rna.tf32.f32 %0, %1;\n" : "=r"(u) : "f"(x));
    return __uint_as_float(u);
}
__device__ __forceinline__ uint32_t fbits(float x) { return __float_as_uint(x); }

__device__ __forceinline__ void mma_tf32(float* c, uint32_t a0, uint32_t a1,
                                         uint32_t a2, uint32_t a3,
                                         uint32_t b0, uint32_t b1) {
    asm volatile(
        "mma.sync.aligned.m16n8k8.row.col.f32.tf32.tf32.f32 "
        "{%0,%1,%2,%3}, {%4,%5,%6,%7}, {%8,%9}, {%0,%1,%2,%3};\n"
        : "+f"(c[0]), "+f"(c[1]), "+f"(c[2]), "+f"(c[3])
        : "r"(a0), "r"(a1), "r"(a2), "r"(a3), "r"(b0), "r"(b1));
}

// exp on the FMA pipe (no MUFU). Valid for x <= 0. ~1e-7 rel.
__device__ __forceinline__ float fast_exp(float x) {
    float t = x * 1.4426950408889634f;
    t = fmaxf(t, -120.f);
    float fn = t + 12582912.f;
    int   n  = __float_as_int(fn) - 0x4B400000;
    float f  = t - (fn - 12582912.f);
    float p  = 1.535336188319500e-4f;
    p = fmaf(p, f, 1.339887440266574e-3f);
    p = fmaf(p, f, 9.618437357674640e-3f);
    p = fmaf(p, f, 5.550332471162809e-2f);
    p = fmaf(p, f, 2.402264791363012e-1f);
    p = fmaf(p, f, 6.931472028550421e-1f);
    p = fmaf(p, f, 1.0f);
    return p * __int_as_float((n + 127) << 23);
}

#define CPA16(dst, src) do { \
    uint32_t _d = (uint32_t)__cvta_generic_to_shared(dst); \
    asm volatile("cp.async.cg.shared.global [%0], [%1], 16;\n" :: "r"(_d), "l"(src)); \
} while (0)

// ---------------- tf32 pre-rounding (weights) ----------------
__global__ void round4_kernel(const float* __restrict__ in, float* __restrict__ out, int n4)
{
    int i = blockIdx.x * blockDim.x + threadIdx.x;
    if (i < n4) {
        float4 v = ((const float4*)in)[i];
        v.x = rtf(v.x); v.y = rtf(v.y); v.z = rtf(v.z); v.w = rtf(v.w);
        ((float4*)out)[i] = v;
    }
}

// ---------------- LayerNorm (outputs tf32-rounded) ----------------
__global__ void ln_kernel(const float* __restrict__ x,
                          const float* __restrict__ g,
                          const float* __restrict__ b,
                          float* __restrict__ out)
{
    int row = blockIdx.x;
    const float* xr = x + (size_t)row * DM;
    float* orow     = out + (size_t)row * DM;
    int t = threadIdx.x;

    float v[4];
    float s = 0.f, sq = 0.f;
#pragma unroll
    for (int i = 0; i < 4; i++) {
        v[i] = xr[t + i * 256];
        s  += v[i];
        sq += v[i] * v[i];
    }
#pragma unroll
    for (int o = 16; o > 0; o >>= 1) {
        s  += __shfl_xor_sync(0xffffffffu, s,  o);
        sq += __shfl_xor_sync(0xffffffffu, sq, o);
    }
    __shared__ float rs[8], rq[8];
    int w = t >> 5, l = t & 31;
    if (l == 0) { rs[w] = s; rq[w] = sq; }
    __syncthreads();
    s = 0.f; sq = 0.f;
#pragma unroll
    for (int i = 0; i < 8; i++) { s += rs[i]; sq += rq[i]; }

    float mean = s * (1.f / DM);
    float var  = sq * (1.f / DM) - mean * mean;
    float rstd = rsqrtf(var + 1e-5f);
#pragma unroll
    for (int i = 0; i < 4; i++) {
        int idx = t + i * 256;
        orow[idx] = rtf((v[i] - mean) * rstd * g[idx] + b[idx]);
    }
}

// ---------------- TF32 GEMM, 3-stage cp.async pipeline (dynamic smem) --------
// C[M,N] = A[M,K] @ W[N,K]^T (+ epilogue). ep: 0=+bias,round; 1=+bias,GELU,round; 2=+bias+R
#define BM 128
#define BN 128
#define BK 16
#define SST 20
#define GEMM_SMEM (3 * (BM + BN) * SST * 4)   // 61440 B

__global__ __launch_bounds__(256, 2)
void gemm_tf32(const float* __restrict__ A, const float* __restrict__ W,
               const float* __restrict__ bias, const float* __restrict__ R,
               float* __restrict__ C, int M, int N, int K, int ep)
{
    extern __shared__ __align__(16) float gsm[];
    float (*As)[BM][SST] = reinterpret_cast<float(*)[BM][SST]>(gsm);
    float (*Ws)[BN][SST] = reinterpret_cast<float(*)[BN][SST]>(gsm + 3 * BM * SST);

    int tid  = threadIdx.x;
    int lane = tid & 31, warp = tid >> 5;
    int wm = warp >> 2, wn = warp & 3;
    int r  = lane >> 2, q = lane & 3;
    int m0 = blockIdx.y * BM, n0 = blockIdx.x * BN;

    int c0r = (tid * 2) >> 2;
    int c0s = ((tid * 2) & 3) * 4;

    float acc[4][4][4];
#pragma unroll
    for (int i = 0; i < 4; i++)
#pragma unroll
        for (int j = 0; j < 4; j++)
#pragma unroll
            for (int c = 0; c < 4; c++) acc[i][j][c] = 0.f;

    const int T = K / BK;
    const float* baseA = A + (size_t)(m0 + c0r) * K + c0s;
    const float* baseW = W + (size_t)(n0 + c0r) * K + c0s;

    // prologue: stages 0 and 1
#pragma unroll
    for (int st = 0; st < 2; st++) {
        const float* srcA = baseA + st * BK;
        const float* srcW = baseW + st * BK;
        CPA16(&As[st][c0r][c0s],     srcA);
        CPA16(&As[st][c0r][c0s + 4], srcA + 4);
        CPA16(&Ws[st][c0r][c0s],     srcW);
        CPA16(&Ws[st][c0r][c0s + 4], srcW + 4);
        asm volatile("cp.async.commit_group;\n");
    }

    for (int kt = 0; kt < T; kt++) {
        asm volatile("cp.async.wait_group 1;\n");   // stage kt resident
        __syncthreads();

        if (kt + 2 < T) {
            int slot = (kt + 2) % 3;
            const float* srcA = baseA + (kt + 2) * BK;
            const float* srcW = baseW + (kt + 2) * BK;
            CPA16(&As[slot][c0r][c0s],     srcA);
            CPA16(&As[slot][c0r][c0s + 4], srcA + 4);
            CPA16(&Ws[slot][c0r][c0s],     srcW);
            CPA16(&Ws[slot][c0r][c0s + 4], srcW + 4);
        }
        asm volatile("cp.async.commit_group;\n");   // uniform group accounting

        int b = kt % 3;
#pragma unroll
        for (int s = 0; s < 2; s++) {
            int k = s * 8;
            uint32_t af[4][4], bf[4][2];
#pragma unroll
            for (int i = 0; i < 4; i++) {
                int mr = wm * 64 + i * 16 + r;
                af[i][0] = fbits(As[b][mr    ][k + q]);
                af[i][1] = fbits(As[b][mr + 8][k + q]);
                af[i][2] = fbits(As[b][mr    ][k + q + 4]);
                af[i][3] = fbits(As[b][mr + 8][k + q + 4]);
            }
#pragma unroll
            for (int j = 0; j < 4; j++) {
                int nr = wn * 32 + j * 8 + r;
                bf[j][0] = fbits(Ws[b][nr][k + q]);
                bf[j][1] = fbits(Ws[b][nr][k + q + 4]);
            }
#pragma unroll
            for (int i = 0; i < 4; i++)
#pragma unroll
                for (int j = 0; j < 4; j++)
                    mma_tf32(acc[i][j], af[i][0], af[i][1], af[i][2], af[i][3],
                             bf[j][0], bf[j][1]);
        }
        // no trailing sync: slot b is only overwritten after the next top sync
    }

    int row0 = m0 + wm * 64 + r;
    int col0 = n0 + wn * 32 + 2 * q;
#pragma unroll
    for (int i = 0; i < 4; i++) {
#pragma unroll
        for (int j = 0; j < 4; j++) {
            int cc = col0 + j * 8;
            float bx = bias[cc], by = bias[cc + 1];
#pragma unroll
            for (int h = 0; h < 2; h++) {
                int rr = row0 + i * 16 + h * 8;
                float vx = acc[i][j][2 * h]     + bx;
                float vy = acc[i][j][2 * h + 1] + by;
                if (ep == 1) {
                    vx = rtf(0.5f * vx * (1.f + erff(vx * 0.70710678118654752f)));
                    vy = rtf(0.5f * vy * (1.f + erff(vy * 0.70710678118654752f)));
                } else if (ep == 2) {
                    const float* rp = R + (size_t)rr * N + cc;
                    vx += rp[0]; vy += rp[1];
                } else {
                    vx = rtf(vx); vy = rtf(vy);
                }
                float2 o2; o2.x = vx; o2.y = vy;
                *(float2*)(C + (size_t)rr * N + cc) = o2;
            }
        }
    }
}

// ---------------- Tensor-core flash attention --------------------------------
// 256 threads = 8 warps = two 64-query tiles sharing a double-buffered K/V stream.
// smem: Qs[128][68] | Ks[2*64][68] | Vs[2*64][68] | Ps[128][68]  = 139264 B
#define ATT_SMEM (512 * 68 * 4)

__global__ __launch_bounds__(256)
void attn_tc(const float* __restrict__ qkv, float* __restrict__ out)
{
    extern __shared__ float sm[];
    float (*Qs)[68] = reinterpret_cast<float(*)[68]>(sm);
    float (*Ks)[68] = reinterpret_cast<float(*)[68]>(sm + 128 * 68);
    float (*Vs)[68] = reinterpret_cast<float(*)[68]>(sm + 256 * 68);
    float (*Ps)[68] = reinterpret_cast<float(*)[68]>(sm + 384 * 68);

    int bh = blockIdx.y;
    int b = bh >> 4, h = bh & 15;
    int q0 = blockIdx.x * 128;
    const float* base = qkv + (size_t)b * SEQ * (3 * DM) + h * HD;

    int tid = threadIdx.x;
    int lane = tid & 31, warp = tid >> 5;
    int r = lane >> 2, q = lane & 3;
    int tile = warp >> 2;                 // 0 or 1
    int wrow = tile * 64 + (warp & 3) * 16;

    // Q tile: 128 rows x 64 cols (already tf32-rounded upstream)
    for (int p = tid; p < 128 * 16; p += 256) {
        int rr = p >> 4, cc = (p & 15) << 2;
        *(float4*)&Qs[rr][cc] = *(const float4*)(base + (size_t)(q0 + rr) * (3 * DM) + cc);
    }

    // prologue: K/V stage 0
    for (int p = tid; p < 64 * 16; p += 256) {
        int rr = p >> 4, cc = (p & 15) << 2;
        const float* kp = base + (size_t)rr * (3 * DM) + cc;
        CPA16(&Ks[rr][cc], kp + DM);
        CPA16(&Vs[rr][cc], kp + 2 * DM);
    }
    asm volatile("cp.async.commit_group;\n");

    float oacc[8][4];
#pragma unroll
    for (int n = 0; n < 8; n++)
#pragma unroll
        for (int c = 0; c < 4; c++) oacc[n][c] = 0.f;
    float m0v = -1e30f, m1v = -1e30f, l0v = 0.f, l1v = 0.f;
    const float scale = 0.125f;
    const int nIter = SEQ / 64;

    for (int it = 0; it < nIter; it++) {
        asm volatile("cp.async.wait_group 0;\n");
        __syncthreads();

        if (it + 1 < nIter) {
            int nb = (it + 1) & 1;
            int k0 = (it + 1) * 64;
            for (int p = tid; p < 64 * 16; p += 256) {
                int rr = p >> 4, cc = (p & 15) << 2;
                const float* kp = base + (size_t)(k0 + rr) * (3 * DM) + cc;
                CPA16(&Ks[nb * 64 + rr][cc], kp + DM);
                CPA16(&Vs[nb * 64 + rr][cc], kp + 2 * DM);
            }
        }
        asm volatile("cp.async.commit_group;\n");

        int kb = (it & 1) * 64;

        // ---- S = Q K^T ----
        float sacc[8][4];
#pragma unroll
        for (int n = 0; n < 8; n++)
#pragma unroll
            for (int c = 0; c < 4; c++) sacc[n][c] = 0.f;

#pragma unroll
        for (int kk = 0; kk < 8; kk++) {
            int k = kk * 8;
            uint32_t a0 = fbits(Qs[wrow + r    ][k + q]);
            uint32_t a1 = fbits(Qs[wrow + r + 8][k + q]);
            uint32_t a2 = fbits(Qs[wrow + r    ][k + q + 4]);
            uint32_t a3 = fbits(Qs[wrow + r + 8][k + q + 4]);
#pragma unroll
            for (int n = 0; n < 8; n++) {
                uint32_t b0 = fbits(Ks[kb + n * 8 + r][k + q]);
                uint32_t b1 = fbits(Ks[kb + n * 8 + r][k + q + 4]);
                mma_tf32(sacc[n], a0, a1, a2, a3, b0, b1);
            }
        }

        // ---- online softmax ----
        float vm0 = -1e30f, vm1 = -1e30f;
#pragma unroll
        for (int n = 0; n < 8; n++) {
            sacc[n][0] *= scale; sacc[n][1] *= scale;
            sacc[n][2] *= scale; sacc[n][3] *= scale;
            vm0 = fmaxf(vm0, fmaxf(sacc[n][0], sacc[n][1]));
            vm1 = fmaxf(vm1, fmaxf(sacc[n][2], sacc[n][3]));
        }
#pragma unroll
        for (int off = 1; off < 4; off <<= 1) {
            vm0 = fmaxf(vm0, __shfl_xor_sync(0xffffffffu, vm0, off));
            vm1 = fmaxf(vm1, __shfl_xor_sync(0xffffffffu, vm1, off));
        }
        float mn0 = fmaxf(m0v, vm0), mn1 = fmaxf(m1v, vm1);
        float al0 = fast_exp(m0v - mn0), al1 = fast_exp(m1v - mn1);
        m0v = mn0; m1v = mn1;

        float rs0 = 0.f, rs1 = 0.f;
#pragma unroll
        for (int n = 0; n < 8; n++) {
            float p00 = rtf(fast_exp(sacc[n][0] - mn0));
            float p01 = rtf(fast_exp(sacc[n][1] - mn0));
            float p10 = rtf(fast_exp(sacc[n][2] - mn1));
            float p11 = rtf(fast_exp(sacc[n][3] - mn1));
            rs0 += p00 + p01;
            rs1 += p10 + p11;
            float2 lo; lo.x = p00; lo.y = p01;
            float2 hi; hi.x = p10; hi.y = p11;
            *(float2*)&Ps[wrow + r    ][n * 8 + 2 * q] = lo;
            *(float2*)&Ps[wrow + r + 8][n * 8 + 2 * q] = hi;
        }
#pragma unroll
        for (int off = 1; off < 4; off <<= 1) {
            rs0 += __shfl_xor_sync(0xffffffffu, rs0, off);
            rs1 += __shfl_xor_sync(0xffffffffu, rs1, off);
        }
        l0v = l0v * al0 + rs0;
        l1v = l1v * al1 + rs1;
#pragma unroll
        for (int n = 0; n < 8; n++) {
            oacc[n][0] *= al0; oacc[n][1] *= al0;
            oacc[n][2] *= al1; oacc[n][3] *= al1;
        }
        __syncwarp();   // Ps rows are per-warp private

        // ---- O += P V ----
#pragma unroll
        for (int kk = 0; kk < 8; kk++) {
            int k = kk * 8;
            uint32_t a0 = fbits(Ps[wrow + r    ][k + q]);
            uint32_t a1 = fbits(Ps[wrow + r + 8][k + q]);
            uint32_t a2 = fbits(Ps[wrow + r    ][k + q + 4]);
            uint32_t a3 = fbits(Ps[wrow + r + 8][k + q + 4]);
#pragma unroll
            for (int n = 0; n < 8; n++) {
                uint32_t b0 = fbits(Vs[kb + k + q    ][n * 8 + r]);
                uint32_t b1 = fbits(Vs[kb + k + q + 4][n * 8 + r]);
                mma_tf32(oacc[n], a0, a1, a2, a3, b0, b1);
            }
        }
    }

    // ---- finalize ----
    float inv0 = __fdividef(1.f, l0v);
    float inv1 = __fdividef(1.f, l1v);
    int row0 = b * SEQ + q0 + wrow + r;
#pragma unroll
    for (int n = 0; n < 8; n++) {
        int col = h * HD + n * 8 + 2 * q;
        float2 lo; lo.x = rtf(oacc[n][0] * inv0); lo.y = rtf(oacc[n][1] * inv0);
        float2 hi; hi.x = rtf(oacc[n][2] * inv1); hi.y = rtf(oacc[n][3] * inv1);
        *(float2*)(out + (size_t)row0 * DM + col)       = lo;
        *(float2*)(out + (size_t)(row0 + 8) * DM + col) = hi;
    }
}

// --------------------------------- launch -----------------------------------
extern "C" void kernel_launch(void* const* d_in, const int* in_sizes, int n_in,
                              void* d_out, int out_size)
{
    const float* x      = (const float*)d_in[0];
    const float* ln1_g  = (const float*)d_in[1];
    const float* ln1_b  = (const float*)d_in[2];
    const float* w_qkv  = (const float*)d_in[3];
    const float* b_qkv  = (const float*)d_in[4];
    const float* w_proj = (const float*)d_in[5];
    const float* b_proj = (const float*)d_in[6];
    const float* ln2_g  = (const float*)d_in[7];
    const float* ln2_b  = (const float*)d_in[8];
    const float* w_fc1  = (const float*)d_in[9];
    const float* b_fc1  = (const float*)d_in[10];
    const float* w_fc2  = (const float*)d_in[11];
    const float* b_fc2  = (const float*)d_in[12];
    float* outp = (float*)d_out;

    float *ln, *qkv, *att, *x1, *ff, *w;
    cudaGetSymbolAddress((void**)&ln,  g_ln);
    cudaGetSymbolAddress((void**)&qkv, g_qkv);
    cudaGetSymbolAddress((void**)&att, g_att);
    cudaGetSymbolAddress((void**)&x1,  g_x1);
    cudaGetSymbolAddress((void**)&ff,  g_ff);
    cudaGetSymbolAddress((void**)&w,   g_w);

    cudaFuncSetAttribute(gemm_tf32, cudaFuncAttributeMaxDynamicSharedMemorySize, GEMM_SMEM);
    cudaFuncSetAttribute(attn_tc,   cudaFuncAttributeMaxDynamicSharedMemorySize, ATT_SMEM);

    round4_kernel<<<(3*DM*DM/4 + 255)/256, 256>>>(w_qkv,  w + WQ_OFF, 3*DM*DM/4);
    round4_kernel<<<(DM*DM/4   + 255)/256, 256>>>(w_proj, w + WP_OFF, DM*DM/4);
    round4_kernel<<<(FFD*DM/4  + 255)/256, 256>>>(w_fc1,  w + W1_OFF, FFD*DM/4);
    round4_kernel<<<(DM*FFD/4  + 255)/256, 256>>>(w_fc2,  w + W2_OFF, DM*FFD/4);

    ln_kernel<<<NTOK, 256>>>(x, ln1_g, ln1_b, ln);
    gemm_tf32<<<dim3(3 * DM / BN, NTOK / BM), 256, GEMM_SMEM>>>(ln, w + WQ_OFF, b_qkv, nullptr, qkv,
                                                                NTOK, 3 * DM, DM, 0);
    attn_tc<<<dim3(SEQ / 128, BATCH * NH), 256, ATT_SMEM>>>(qkv, att);
    gemm_tf32<<<dim3(DM / BN, NTOK / BM), 256, GEMM_SMEM>>>(att, w + WP_OFF, b_proj, x, x1,
                                                            NTOK, DM, DM, 2);
    ln_kernel<<<NTOK, 256>>>(x1, ln2_g, ln2_b, ln);
    gemm_tf32<<<dim3(FFD / BN, NTOK / BM), 256, GEMM_SMEM>>>(ln, w + W1_OFF, b_fc1, nullptr, ff,
                                                             NTOK, FFD, DM, 1);
    gemm_tf32<<<dim3(DM / BN, NTOK / BM), 256, GEMM_SMEM>>>(ff, w + W2_OFF, b_fc2, x1, outp,
                                                            NTOK, DM, FFD, 2);
}